// round 14
// baseline (speedup 1.0000x reference)
#include <cuda_runtime.h>
#include <cuda_bf16.h>

#define BB 8
#define NN 2048
#define NPAD (NN + 512)
#define BIGF 1e30f

// chamfer shape (R13 geometry)
#define TB     128
#define QPT    2
#define QSTEP  (QPT * TB)        // 256 query slots per pass
#define GQ     4
#define RSPLIT 32
#define RTILE  64                // max rlen = ceil(2048/32)
#define GZ     (2 * BB)          // 16 tasks
#define ARR_PER_TASK (GQ * RSPLIT)   // 128 arrivals per task

typedef unsigned long long u64;

// Scratch (allocation-free). Points transformed: (x+y, x-y, z, 0).
// g_valid[0]=clean(points+target), g_valid[1]=predp(points+pred)
__device__ __align__(16) float4       g_valid[2][BB][NPAD];
__device__ __align__(16) unsigned int g_minbits[2][BB][NN];
__device__ int          g_cnt[BB];
__device__ float        g_l1part[128];
__device__ float        g_tasksum[GZ];
__device__ unsigned int g_done_task[GZ];
__device__ unsigned int g_done;

// ---- packed f32x2 helpers (Blackwell dual-fp32 pipe) ----
__device__ __forceinline__ u64 addf32x2(u64 a, u64 b) {
    u64 r; asm("add.rn.f32x2 %0, %1, %2;" : "=l"(r) : "l"(a), "l"(b)); return r;
}
__device__ __forceinline__ u64 packf2(float lo, float hi) {
    u64 r; asm("mov.b64 %0, {%1, %2};" : "=l"(r) : "f"(lo), "f"(hi)); return r;
}
__device__ __forceinline__ void unpackf2(u64 v, float& lo, float& hi) {
    asm("mov.b64 {%0, %1}, %2;" : "=f"(lo), "=f"(hi) : "l"(v));
}

// ---------------------------------------------------------------------------
// Kernel 1: prep — 128 blocks x 128 threads, one point per thread.
// ---------------------------------------------------------------------------
__global__ void __launch_bounds__(128)
prep_kernel(const float* __restrict__ pred,
            const float* __restrict__ target,
            const int*   __restrict__ mask,
            const float* __restrict__ points) {
    int bid = blockIdx.x, tid = threadIdx.x;
    int b = bid >> 4, s = bid & 15;
    int n  = s * 128 + tid;
    int gi = b * NN + n;

    const float* pp = pred   + gi * 3;
    const float* tt = target + gi * 3;
    const float* xx = points + gi * 3;
    float p0 = pp[0], p1 = pp[1], p2 = pp[2];
    float t0 = tt[0], t1 = tt[1], t2 = tt[2];
    float x0 = xx[0], x1 = xx[1], x2 = xx[2];
    int m = mask[gi];

    const unsigned bigbits = __float_as_uint(BIGF);
    g_minbits[0][b][n] = bigbits;
    g_minbits[1][b][n] = bigbits;

    float c0 = x0 + t0, c1 = x1 + t1, c2 = x2 + t2;   // clean
    float q0 = x0 + p0, q1 = x1 + p1, q2 = x2 + p2;   // predp
    float l1 = 0.f;

    __shared__ int sh_cnt, sh_base;
    if (tid == 0) sh_cnt = 0;
    __syncthreads();
    int klocal = -1;
    if (m) {
        l1 = fabsf(p0 - t0) + fabsf(p1 - t1) + fabsf(p2 - t2);
        klocal = atomicAdd(&sh_cnt, 1);
    }
    __syncthreads();
    if (tid == 0) sh_base = atomicAdd(&g_cnt[b], sh_cnt);

    __shared__ float wsum[4];
#pragma unroll
    for (int o = 16; o > 0; o >>= 1) l1 += __shfl_down_sync(0xffffffffu, l1, o);
    if ((tid & 31) == 0) wsum[tid >> 5] = l1;
    __syncthreads();
    if (tid == 0)
        g_l1part[bid] = wsum[0] + wsum[1] + wsum[2] + wsum[3];

    if (m) {
        int k = sh_base + klocal;
        g_valid[0][b][k] = make_float4(c0 + c1, c0 - c1, c2, 0.f);
        g_valid[1][b][k] = make_float4(q0 + q1, q0 - q1, q2, 0.f);
    }
}

// ---------------------------------------------------------------------------
// Kernel 2: chamfer, grid (4, 32, 16) = 2048 blocks, TB=128.
// Two queries packed per f32x2; tile holds negated broadcast-packed refs.
// |dx|+|dy|+|dz| == max(|du|,|dv|) + |dz| with (u,v) = (x+y, x-y).
// ---------------------------------------------------------------------------
__global__ void __launch_bounds__(TB)
chamfer_kernel(float* __restrict__ out) {
    int tid  = threadIdx.x;
    int task = blockIdx.z;
    int b    = task >> 1;
    int dir  = task & 1;               // 0: clean->pred, 1: pred->clean
    int cnt  = g_cnt[b];

    __shared__ ulonglong2 tileUV[RTILE];   // x=(-u,-u), y=(-v,-v)
    __shared__ u64        tileZ[RTILE];    // (-z,-z)

    int qn   = (cnt + GQ - 1) / GQ;            // ~256
    int q_lo = blockIdx.x * qn;
    int q_hi = min(q_lo + qn, cnt);
    int rn   = (cnt + RSPLIT - 1) / RSPLIT;    // <= 64
    int r_lo = blockIdx.y * rn;
    int rlen = min(rn, cnt - r_lo);

    if (q_lo < cnt && rlen > 0) {
        const float4* __restrict__ Q = g_valid[dir][b];
        const float4* __restrict__ R = g_valid[dir ^ 1][b];
        unsigned int* __restrict__ M = g_minbits[dir][b];

        if (tid < RTILE) {
            float4 p = (tid < rlen) ? R[r_lo + tid]
                                    : make_float4(BIGF, BIGF, BIGF, 0.f);
            float nu = -p.x, nv = -p.y, nz = -p.z;
            tileUV[tid] = make_ulonglong2(packf2(nu, nu), packf2(nv, nv));
            tileZ[tid]  = packf2(nz, nz);
        }
        __syncthreads();

        for (int q0b = q_lo; q0b < q_hi; q0b += QSTEP) {   // 1 pass typical
            int qi0 = q0b + tid;           // unguarded: g_valid padded past NN
            int qi1 = qi0 + TB;
            float4 v0 = Q[qi0];
            float4 v1 = Q[qi1];
            u64 qu = packf2(v0.x, v1.x);   // 3 packs per pass, amortized
            u64 qv = packf2(v0.y, v1.y);
            u64 qz = packf2(v0.z, v1.z);
            float mn0 = BIGF, mn1 = BIGF;

#pragma unroll 8
            for (int j = 0; j < rlen; ++j) {
                ulonglong2 yuv = tileUV[j];        // LDS.128 broadcast
                u64 yz         = tileZ[j];         // LDS.64 broadcast
                u64 du = addf32x2(qu, yuv.x);      // (q0u-yu, q1u-yu)
                u64 dv = addf32x2(qv, yuv.y);
                u64 dz = addf32x2(qz, yz);
                float du0, du1, dv0, dv1, dz0, dz1;
                unpackf2(du, du0, du1);
                unpackf2(dv, dv0, dv1);
                unpackf2(dz, dz0, dz1);
                float d0 = fmaxf(fabsf(du0), fabsf(dv0)) + fabsf(dz0);
                mn0 = fminf(mn0, d0);
                float d1 = fmaxf(fabsf(du1), fabsf(dv1)) + fabsf(dz1);
                mn1 = fminf(mn1, d1);
            }

            if (qi0 < q_hi) atomicMin(&M[qi0], __float_as_uint(mn0));
            if (qi1 < q_hi) atomicMin(&M[qi1], __float_as_uint(mn1));
        }
    }

    // -------- hierarchical arrive --------
    __threadfence();
    __syncthreads();
    __shared__ int task_last;
    if (tid == 0)
        task_last = (atomicAdd(&g_done_task[task], 1u) == ARR_PER_TASK - 1);
    __syncthreads();
    if (!task_last) return;

    // -------- per-task tail: reduce this (dir,b) min array to one scalar ----
    __threadfence();
    {
        const uint4* __restrict__ p = (const uint4*)g_minbits[dir][b];
        int nv4 = cnt >> 2;
        float s = 0.f;
        for (int k = tid; k < nv4; k += TB) {
            uint4 u = p[k];
            s += (__uint_as_float(u.x) + __uint_as_float(u.y))
               + (__uint_as_float(u.z) + __uint_as_float(u.w));
        }
        if (tid < (cnt & 3))
            s += __uint_as_float(g_minbits[dir][b][(cnt & ~3) + tid]);

        __shared__ float wsum[4];
#pragma unroll
        for (int o = 16; o > 0; o >>= 1) s += __shfl_down_sync(0xffffffffu, s, o);
        if ((tid & 31) == 0) wsum[tid >> 5] = s;
        __syncthreads();
        if (tid == 0)
            g_tasksum[task] = wsum[0] + wsum[1] + wsum[2] + wsum[3];
    }

    // -------- global arrive; last task-block combines --------
    __threadfence();
    __syncthreads();
    __shared__ int is_last;
    if (tid == 0)
        is_last = (atomicAdd(&g_done, 1u) == GZ - 1);
    __syncthreads();
    if (!is_last) return;

    __threadfence();
    float l1p = g_l1part[tid];             // 128 partials, TB == 128
    __shared__ float wl[4];
#pragma unroll
    for (int o = 16; o > 0; o >>= 1) l1p += __shfl_down_sync(0xffffffffu, l1p, o);
    if ((tid & 31) == 0) wl[tid >> 5] = l1p;
    __syncthreads();
    if (tid == 0) {
        float cdsum = 0.f;
#pragma unroll
        for (int t = 0; t < GZ; ++t)
            cdsum += g_tasksum[t] / (float)g_cnt[t >> 1];
        float l1num = wl[0] + wl[1] + wl[2] + wl[3];
        int msum = 0;
#pragma unroll
        for (int bb = 0; bb < BB; ++bb) msum += g_cnt[bb];
        float l1 = l1num / 3.0f / (float)msum;
        float cd = cdsum / (float)BB;
        out[0] = l1 + expf(-l1) * cd;
        g_done = 0;                        // reset for next graph replay
    }
    __syncthreads();
    if (tid < BB)  g_cnt[tid] = 0;
    if (tid < GZ)  g_done_task[tid] = 0;
}

// ---------------------------------------------------------------------------
extern "C" void kernel_launch(void* const* d_in, const int* in_sizes, int n_in,
                              void* d_out, int out_size) {
    const float* pred   = (const float*)d_in[0];
    const float* target = (const float*)d_in[1];
    const int*   mask   = (const int*)  d_in[2];
    const float* points = (const float*)d_in[3];
    float* out = (float*)d_out;

    prep_kernel<<<128, 128>>>(pred, target, mask, points);

    dim3 grid(GQ, RSPLIT, GZ);   // (4, 32, 16) = 2048 blocks, all live
    chamfer_kernel<<<grid, TB>>>(out);
}